// round 1
// baseline (speedup 1.0000x reference)
#include <cuda_runtime.h>
#include <math.h>

#define MAXB 8192
#define NS   32
#define D128 128
#define MARGIN 0.8f
#define EPS 1e-6f

__device__ float g_sq[MAXB];
__device__ int   g_cnt[NS];
__device__ int   g_start[NS + 1];
__device__ int   g_ofs[NS];
__device__ int   g_order[MAXB];
__device__ float g_rowloss[MAXB];
__device__ float g_rowvalid[MAXB];

// ---------------- K0: zero histogram ----------------
__global__ void k_zero() {
    if (threadIdx.x < NS) g_cnt[threadIdx.x] = 0;
}

// ---------------- K1: per-row squared norm + subject histogram ----------------
__global__ void k_prep(const float* __restrict__ emb, const int* __restrict__ sbj, int B) {
    int row = blockIdx.x * (blockDim.x >> 5) + (threadIdx.x >> 5);
    if (row >= B) return;
    int lane = threadIdx.x & 31;
    float s = 0.f;
    const float* e = emb + (size_t)row * D128;
    #pragma unroll
    for (int k = lane; k < D128; k += 32) { float v = e[k]; s = fmaf(v, v, s); }
    #pragma unroll
    for (int off = 16; off > 0; off >>= 1) s += __shfl_xor_sync(0xffffffff, s, off);
    if (lane == 0) {
        g_sq[row] = s;
        int sj = sbj[row]; sj = min(max(sj, 0), NS - 1);
        atomicAdd(&g_cnt[sj], 1);
    }
}

// ---------------- K2: prefix sum over subjects ----------------
__global__ void k_prefix() {
    if (threadIdx.x == 0) {
        int acc = 0;
        for (int s = 0; s < NS; s++) { g_start[s] = acc; g_ofs[s] = acc; acc += g_cnt[s]; }
        g_start[NS] = acc;
    }
}

// ---------------- K3: scatter rows into subject-sorted order ----------------
__global__ void k_scatter(const int* __restrict__ sbj, int B) {
    int i = blockIdx.x * blockDim.x + threadIdx.x;
    if (i < B) {
        int s = sbj[i]; s = min(max(s, 0), NS - 1);
        int p = atomicAdd(&g_ofs[s], 1);
        g_order[p] = i;
    }
}

// ---------------- K4: fused mining + triplet epilogue ----------------
// One block = 32 consecutive rows in subject-sorted order. 64 threads,
// each computes a 4x4 register tile of the 32x32 dot-product chunk.
#define API 36   // padded pitch for shared tiles (float4-aligned, conflict-free)

__global__ void __launch_bounds__(64) k_mine(const float* __restrict__ emb,
                                             const int* __restrict__ labels,
                                             const int* __restrict__ sbj, int B) {
    __shared__ float As[D128 * API];
    __shared__ float Bs[D128 * API];
    __shared__ int   rId[32], rLab[32], rSbj[32];
    __shared__ float rSq[32];
    __shared__ int   cJ[32], cLab[32], cSbj[32];
    __shared__ float cSq[32];
    __shared__ float redV[32 * 8];
    __shared__ int   redI[32 * 8];
    __shared__ float bestPV[32], bestNV[32];
    __shared__ int   bestPI[32], bestNI[32];
    __shared__ int   sJlo, sJhi;

    const int tid = threadIdx.x;
    const int tileBase = blockIdx.x * 32;

    if (tid < 32) {
        int p = tileBase + tid;
        int i = g_order[p];
        rId[tid] = i;
        rLab[tid] = labels[i];
        int s = sbj[i]; s = min(max(s, 0), NS - 1);
        rSbj[tid] = s;
        rSq[tid] = g_sq[i];
    }
    __syncthreads();
    if (tid == 0) {
        int lo = g_start[rSbj[0]], hi = g_start[rSbj[0] + 1];
        for (int r = 1; r < 32; r++) {
            lo = min(lo, g_start[rSbj[r]]);
            hi = max(hi, g_start[rSbj[r] + 1]);
        }
        sJlo = lo; sJhi = hi;
    }
    // Load A tile transposed: As[k*API + r]
    for (int idx = tid; idx < 32 * D128; idx += 64) {
        int r = idx >> 7, k = idx & 127;
        As[k * API + r] = emb[(size_t)rId[r] * D128 + k];
    }
    __syncthreads();

    const int tx = tid & 7, ty = tid >> 3;   // 8x8 thread grid, 4x4 per thread
    float bpV[4], bnV[4];
    int   bpI[4], bnI[4];
    #pragma unroll
    for (int r = 0; r < 4; r++) { bpV[r] = -3.0e38f; bnV[r] = 3.0e38f; bpI[r] = -1; bnI[r] = -1; }

    const int jlo = sJlo, jhi = sJhi;
    for (int jc = jlo; jc < jhi; jc += 32) {
        int nj = min(32, jhi - jc);
        __syncthreads();   // previous chunk's compute done before overwriting Bs
        if (tid < 32) {
            if (tid < nj) {
                int j = g_order[jc + tid];
                cJ[tid] = j; cLab[tid] = labels[j];
                int s = sbj[j]; cSbj[tid] = min(max(s, 0), NS - 1);
                cSq[tid] = g_sq[j];
            } else { cJ[tid] = -1; cSbj[tid] = -9; }
        }
        for (int idx = tid; idx < 32 * D128; idx += 64) {
            int r = idx >> 7, k = idx & 127;
            float v = 0.f;
            if (r < nj) {
                int j = g_order[jc + r];
                v = emb[(size_t)j * D128 + k];
            }
            Bs[k * API + r] = v;
        }
        __syncthreads();

        float acc[4][4];
        #pragma unroll
        for (int r = 0; r < 4; r++)
            #pragma unroll
            for (int c = 0; c < 4; c++) acc[r][c] = 0.f;

        #pragma unroll 4
        for (int k = 0; k < D128; k++) {
            const float4 a = *reinterpret_cast<const float4*>(&As[k * API + 4 * ty]);
            const float4 b = *reinterpret_cast<const float4*>(&Bs[k * API + 4 * tx]);
            float av[4] = {a.x, a.y, a.z, a.w};
            float bv[4] = {b.x, b.y, b.z, b.w};
            #pragma unroll
            for (int r = 0; r < 4; r++)
                #pragma unroll
                for (int c = 0; c < 4; c++)
                    acc[r][c] = fmaf(av[r], bv[c], acc[r][c]);
        }

        #pragma unroll
        for (int r = 0; r < 4; r++) {
            int rr = 4 * ty + r;
            #pragma unroll
            for (int c = 0; c < 4; c++) {
                int cc = 4 * tx + c;
                if (cc >= nj) continue;
                if (cSbj[cc] != rSbj[rr]) continue;
                int j = cJ[cc];
                float d2 = rSq[rr] + cSq[cc] - 2.f * acc[r][c];
                if (cLab[cc] == rLab[rr]) {
                    if (j != rId[rr] && d2 > bpV[r]) { bpV[r] = d2; bpI[r] = j; }
                } else {
                    if (d2 < bnV[r]) { bnV[r] = d2; bnI[r] = j; }
                }
            }
        }
    }

    // Reduce hardest-positive across the 8 tx threads per row
    __syncthreads();
    #pragma unroll
    for (int r = 0; r < 4; r++) { redV[(4 * ty + r) * 8 + tx] = bpV[r]; redI[(4 * ty + r) * 8 + tx] = bpI[r]; }
    __syncthreads();
    if (tid < 32) {
        float bv = -3.0e38f; int bi = -1;
        for (int t = 0; t < 8; t++) {
            float v = redV[tid * 8 + t];
            if (v > bv) { bv = v; bi = redI[tid * 8 + t]; }
        }
        bestPV[tid] = bv; bestPI[tid] = bi;
    }
    __syncthreads();
    // Reduce hardest-negative
    #pragma unroll
    for (int r = 0; r < 4; r++) { redV[(4 * ty + r) * 8 + tx] = bnV[r]; redI[(4 * ty + r) * 8 + tx] = bnI[r]; }
    __syncthreads();
    if (tid < 32) {
        float bv = 3.0e38f; int bi = -1;
        for (int t = 0; t < 8; t++) {
            float v = redV[tid * 8 + t];
            if (v < bv) { bv = v; bi = redI[tid * 8 + t]; }
        }
        bestNV[tid] = bv; bestNI[tid] = bi;
    }
    __syncthreads();

    // Epilogue: per-row triplet margin loss. 2 warps, 16 rows each.
    int w = tid >> 5, lane = tid & 31;
    for (int rr = 16 * w; rr < 16 * w + 16; rr++) {
        bool valid = (bestPI[rr] >= 0) && (bestNI[rr] >= 0);
        float per = 0.f;
        if (valid) {
            int pi = bestPI[rr], ni = bestNI[rr];
            const float* ep = emb + (size_t)pi * D128;
            const float* en = emb + (size_t)ni * D128;
            float sp = 0.f, sn = 0.f;
            #pragma unroll
            for (int k = lane; k < D128; k += 32) {
                float a = As[k * API + rr];
                float dp = a - ep[k] + EPS; sp = fmaf(dp, dp, sp);
                float dn = a - en[k] + EPS; sn = fmaf(dn, dn, sn);
            }
            #pragma unroll
            for (int off = 16; off > 0; off >>= 1) {
                sp += __shfl_xor_sync(0xffffffff, sp, off);
                sn += __shfl_xor_sync(0xffffffff, sn, off);
            }
            per = fmaxf(sqrtf(sp) - sqrtf(sn) + MARGIN, 0.f);
        }
        if (lane == 0) {
            int i = rId[rr];
            g_rowloss[i]  = per;
            g_rowvalid[i] = valid ? 1.f : 0.f;
        }
    }
}

// ---------------- K5: deterministic final reduction ----------------
__global__ void k_reduce(float* __restrict__ out, int B) {
    __shared__ float sl[256], sv[256];
    int tid = threadIdx.x;
    float l = 0.f, v = 0.f;
    for (int i = tid; i < B; i += 256) { l += g_rowloss[i]; v += g_rowvalid[i]; }
    sl[tid] = l; sv[tid] = v;
    __syncthreads();
    for (int off = 128; off > 0; off >>= 1) {
        if (tid < off) { sl[tid] += sl[tid + off]; sv[tid] += sv[tid + off]; }
        __syncthreads();
    }
    if (tid == 0) {
        float cnt = sv[0];
        out[0] = (cnt > 0.f) ? (sl[0] / fmaxf(cnt, 1.f)) : 0.f;
    }
}

extern "C" void kernel_launch(void* const* d_in, const int* in_sizes, int n_in,
                              void* d_out, int out_size) {
    const float* emb   = (const float*)d_in[0];
    const int* labels  = (const int*)d_in[1];
    const int* sbj     = (const int*)d_in[2];
    float* out = (float*)d_out;
    int B = in_sizes[1];

    k_zero<<<1, 32>>>();
    k_prep<<<(B + 7) / 8, 256>>>(emb, sbj, B);
    k_prefix<<<1, 32>>>();
    k_scatter<<<(B + 255) / 256, 256>>>(sbj, B);
    k_mine<<<B / 32, 64>>>(emb, labels, sbj, B);
    k_reduce<<<1, 256>>>(out, B);
}

// round 2
// speedup vs baseline: 2.4678x; 2.4678x over previous
#include <cuda_runtime.h>
#include <math.h>

#define MAXB 8192
#define NS   32
#define SEG  4
#define D128 128
#define MARGIN 0.8f
#define EPS 1e-6f

__device__ float g_sq[MAXB];
__device__ int   g_cnt[NS];
__device__ int   g_start[NS + 1];
__device__ int   g_ofs[NS];
__device__ int   g_order[MAXB];
__device__ float g_pV[SEG * MAXB];
__device__ int   g_pI[SEG * MAXB];
__device__ float g_nV[SEG * MAXB];
__device__ int   g_nI[SEG * MAXB];
__device__ float g_blkL[MAXB / 8];
__device__ float g_blkV[MAXB / 8];

// ---------------- K0: zero histogram ----------------
__global__ void k_zero() {
    if (threadIdx.x < NS) g_cnt[threadIdx.x] = 0;
}

// ---------------- K1: per-row squared norm + subject histogram ----------------
__global__ void k_prep(const float* __restrict__ emb, const int* __restrict__ sbj, int B) {
    int row = blockIdx.x * (blockDim.x >> 5) + (threadIdx.x >> 5);
    if (row >= B) return;
    int lane = threadIdx.x & 31;
    const float4 v4 = reinterpret_cast<const float4*>(emb + (size_t)row * D128)[lane];
    float s = v4.x * v4.x + v4.y * v4.y + v4.z * v4.z + v4.w * v4.w;
    #pragma unroll
    for (int off = 16; off > 0; off >>= 1) s += __shfl_xor_sync(0xffffffff, s, off);
    if (lane == 0) {
        g_sq[row] = s;
        int sj = sbj[row]; sj = min(max(sj, 0), NS - 1);
        atomicAdd(&g_cnt[sj], 1);
    }
}

// ---------------- K2: prefix sum over subjects ----------------
__global__ void k_prefix() {
    if (threadIdx.x == 0) {
        int acc = 0;
        for (int s = 0; s < NS; s++) { g_start[s] = acc; g_ofs[s] = acc; acc += g_cnt[s]; }
        g_start[NS] = acc;
    }
}

// ---------------- K3: scatter rows into subject-sorted order ----------------
__global__ void k_scatter(const int* __restrict__ sbj, int B) {
    int i = blockIdx.x * blockDim.x + threadIdx.x;
    if (i < B) {
        int s = sbj[i]; s = min(max(s, 0), NS - 1);
        int p = atomicAdd(&g_ofs[s], 1);
        g_order[p] = i;
    }
}

// ---------------- K4: segmented mining ----------------
// grid (B/32 row-tiles, SEG col-segments), 128 threads.
// Tile: 32 rows x 64 cols, thread grid 16(tx) x 8(ty), 4x4 per thread.
// K=128 processed in two 64-halves to keep static smem under 48KB.
#define API 36
#define BPI 68

__global__ void __launch_bounds__(128) k_mine(const float* __restrict__ emb,
                                              const int* __restrict__ labels,
                                              const int* __restrict__ sbj, int B) {
    __shared__ float As[D128 * API];          // full-K A tile, transposed
    __shared__ float Bs[64 * BPI];            // half-K B tile, transposed
    __shared__ int   rId[32], rLab[32], rSbj[32];
    __shared__ float rSq[32];
    __shared__ int   cJ[64], cLab[64], cSbj[64];
    __shared__ float cSq[64];
    __shared__ float redV[32 * 16];
    __shared__ int   redI[32 * 16];
    __shared__ int   sJlo, sJhi;

    const int tid = threadIdx.x;
    const int tileBase = blockIdx.x * 32;
    const int seg = blockIdx.y;

    if (tid < 32) {
        int i = g_order[tileBase + tid];
        rId[tid] = i;
        rLab[tid] = labels[i];
        int s = sbj[i]; s = min(max(s, 0), NS - 1);
        rSbj[tid] = s;
        rSq[tid] = g_sq[i];
    }
    __syncthreads();
    if (tid == 0) {
        int lo = g_start[rSbj[0]], hi = g_start[rSbj[0] + 1];
        for (int r = 1; r < 32; r++) {
            lo = min(lo, g_start[rSbj[r]]);
            hi = max(hi, g_start[rSbj[r] + 1]);
        }
        sJlo = lo; sJhi = hi;
    }
    // Load full A tile transposed, coalesced gmem (k fastest).
    for (int idx = tid; idx < 32 * D128; idx += 128) {
        int r = idx >> 7, k = idx & 127;
        As[k * API + r] = emb[(size_t)rId[r] * D128 + k];
    }
    __syncthreads();

    const int tx = tid & 15, ty = tid >> 4;
    float bpV[4], bnV[4];
    int   bpI[4], bnI[4];
    #pragma unroll
    for (int r = 0; r < 4; r++) { bpV[r] = -3.0e38f; bnV[r] = 3.0e38f; bpI[r] = -1; bnI[r] = -1; }

    const int len = sJhi - sJlo;
    const int per = (len + SEG - 1) / SEG;
    const int lo  = sJlo + seg * per;
    const int hi  = min(lo + per, sJhi);

    for (int jc = lo; jc < hi; jc += 64) {
        const int nj = min(64, hi - jc);
        __syncthreads();     // previous selection done reading col meta
        if (tid < 64) {
            if (tid < nj) {
                int j = g_order[jc + tid];
                cJ[tid] = j; cLab[tid] = labels[j];
                int s = sbj[j]; cSbj[tid] = min(max(s, 0), NS - 1);
                cSq[tid] = g_sq[j];
            } else { cJ[tid] = -1; cSbj[tid] = -9; }
        }

        float acc[4][4];
        #pragma unroll
        for (int r = 0; r < 4; r++)
            #pragma unroll
            for (int c = 0; c < 4; c++) acc[r][c] = 0.f;

        #pragma unroll
        for (int kh = 0; kh < D128; kh += 64) {
            __syncthreads();   // prior compute done reading Bs
            for (int idx = tid; idx < 64 * 64; idx += 128) {
                int c = idx >> 6, k = idx & 63;
                float v = 0.f;
                if (c < nj) v = emb[(size_t)g_order[jc + c] * D128 + kh + k];
                Bs[k * BPI + c] = v;
            }
            __syncthreads();

            #pragma unroll 4
            for (int k = 0; k < 64; k++) {
                const float4 a = *reinterpret_cast<const float4*>(&As[(kh + k) * API + 4 * ty]);
                const float4 b = *reinterpret_cast<const float4*>(&Bs[k * BPI + 4 * tx]);
                float av[4] = {a.x, a.y, a.z, a.w};
                float bv[4] = {b.x, b.y, b.z, b.w};
                #pragma unroll
                for (int r = 0; r < 4; r++)
                    #pragma unroll
                    for (int c = 0; c < 4; c++)
                        acc[r][c] = fmaf(av[r], bv[c], acc[r][c]);
            }
        }

        #pragma unroll
        for (int r = 0; r < 4; r++) {
            int rr = 4 * ty + r;
            #pragma unroll
            for (int c = 0; c < 4; c++) {
                int cc = 4 * tx + c;
                if (cc >= nj) continue;
                if (cSbj[cc] != rSbj[rr]) continue;
                int j = cJ[cc];
                float d2 = rSq[rr] + cSq[cc] - 2.f * acc[r][c];
                if (cLab[cc] == rLab[rr]) {
                    if (j != rId[rr] && d2 > bpV[r]) { bpV[r] = d2; bpI[r] = j; }
                } else {
                    if (d2 < bnV[r]) { bnV[r] = d2; bnI[r] = j; }
                }
            }
        }
    }

    // Reduce across 16 tx threads per row: positives
    __syncthreads();
    #pragma unroll
    for (int r = 0; r < 4; r++) { redV[(4 * ty + r) * 16 + tx] = bpV[r]; redI[(4 * ty + r) * 16 + tx] = bpI[r]; }
    __syncthreads();
    if (tid < 32) {
        float bv = -3.0e38f; int bi = -1;
        #pragma unroll
        for (int t = 0; t < 16; t++) {
            float v = redV[tid * 16 + t];
            if (v > bv) { bv = v; bi = redI[tid * 16 + t]; }
        }
        g_pV[seg * MAXB + rId[tid]] = bv;
        g_pI[seg * MAXB + rId[tid]] = bi;
    }
    __syncthreads();
    // negatives
    #pragma unroll
    for (int r = 0; r < 4; r++) { redV[(4 * ty + r) * 16 + tx] = bnV[r]; redI[(4 * ty + r) * 16 + tx] = bnI[r]; }
    __syncthreads();
    if (tid < 32) {
        float bv = 3.0e38f; int bi = -1;
        #pragma unroll
        for (int t = 0; t < 16; t++) {
            float v = redV[tid * 16 + t];
            if (v < bv) { bv = v; bi = redI[tid * 16 + t]; }
        }
        g_nV[seg * MAXB + rId[tid]] = bv;
        g_nI[seg * MAXB + rId[tid]] = bi;
    }
}

// ---------------- K5: merge segments + triplet epilogue ----------------
// 256 threads = 8 warps, one row per warp. Block partial sums to globals.
__global__ void __launch_bounds__(256) k_merge(const float* __restrict__ emb, int B) {
    __shared__ float sL[8], sV[8];
    int w = threadIdx.x >> 5, lane = threadIdx.x & 31;
    int i = blockIdx.x * 8 + w;
    float per = 0.f, val = 0.f;
    if (i < B) {
        int bpI = -1, bnI = -1;
        if (lane == 0) {
            float bpV = -3.0e38f, bnV = 3.0e38f;
            #pragma unroll
            for (int s = 0; s < SEG; s++) {
                float pv = g_pV[s * MAXB + i]; int pi = g_pI[s * MAXB + i];
                if (pi >= 0 && pv > bpV) { bpV = pv; bpI = pi; }
                float nv = g_nV[s * MAXB + i]; int ni = g_nI[s * MAXB + i];
                if (ni >= 0 && nv < bnV) { bnV = nv; bnI = ni; }
            }
        }
        bpI = __shfl_sync(0xffffffff, bpI, 0);
        bnI = __shfl_sync(0xffffffff, bnI, 0);
        if (bpI >= 0 && bnI >= 0) {
            const float4 a = reinterpret_cast<const float4*>(emb + (size_t)i   * D128)[lane];
            const float4 p = reinterpret_cast<const float4*>(emb + (size_t)bpI * D128)[lane];
            const float4 n = reinterpret_cast<const float4*>(emb + (size_t)bnI * D128)[lane];
            float dx, sp, sn;
            dx = a.x - p.x + EPS; sp = dx * dx;
            dx = a.y - p.y + EPS; sp = fmaf(dx, dx, sp);
            dx = a.z - p.z + EPS; sp = fmaf(dx, dx, sp);
            dx = a.w - p.w + EPS; sp = fmaf(dx, dx, sp);
            dx = a.x - n.x + EPS; sn = dx * dx;
            dx = a.y - n.y + EPS; sn = fmaf(dx, dx, sn);
            dx = a.z - n.z + EPS; sn = fmaf(dx, dx, sn);
            dx = a.w - n.w + EPS; sn = fmaf(dx, dx, sn);
            #pragma unroll
            for (int off = 16; off > 0; off >>= 1) {
                sp += __shfl_xor_sync(0xffffffff, sp, off);
                sn += __shfl_xor_sync(0xffffffff, sn, off);
            }
            per = fmaxf(sqrtf(sp) - sqrtf(sn) + MARGIN, 0.f);
            val = 1.f;
        }
    }
    if (lane == 0) { sL[w] = per; sV[w] = val; }
    __syncthreads();
    if (threadIdx.x == 0) {
        float l = 0.f, v = 0.f;
        #pragma unroll
        for (int t = 0; t < 8; t++) { l += sL[t]; v += sV[t]; }
        g_blkL[blockIdx.x] = l;
        g_blkV[blockIdx.x] = v;
    }
}

// ---------------- K6: deterministic final reduction ----------------
__global__ void k_final(float* __restrict__ out, int nblk) {
    __shared__ float sl[1024], sv[1024];
    int tid = threadIdx.x;
    float l = 0.f, v = 0.f;
    for (int i = tid; i < nblk; i += 1024) { l += g_blkL[i]; v += g_blkV[i]; }
    sl[tid] = l; sv[tid] = v;
    __syncthreads();
    for (int off = 512; off > 0; off >>= 1) {
        if (tid < off) { sl[tid] += sl[tid + off]; sv[tid] += sv[tid + off]; }
        __syncthreads();
    }
    if (tid == 0) {
        float cnt = sv[0];
        out[0] = (cnt > 0.f) ? (sl[0] / fmaxf(cnt, 1.f)) : 0.f;
    }
}

extern "C" void kernel_launch(void* const* d_in, const int* in_sizes, int n_in,
                              void* d_out, int out_size) {
    const float* emb   = (const float*)d_in[0];
    const int* labels  = (const int*)d_in[1];
    const int* sbj     = (const int*)d_in[2];
    float* out = (float*)d_out;
    int B = in_sizes[1];

    k_zero<<<1, 32>>>();
    k_prep<<<(B + 7) / 8, 256>>>(emb, sbj, B);
    k_prefix<<<1, 32>>>();
    k_scatter<<<(B + 255) / 256, 256>>>(sbj, B);
    dim3 mgrid(B / 32, SEG);
    k_mine<<<mgrid, 128>>>(emb, labels, sbj, B);
    int nblk = (B + 7) / 8;
    k_merge<<<nblk, 256>>>(emb, B);
    k_final<<<1, 1024>>>(out, nblk);
}

// round 3
// speedup vs baseline: 2.6329x; 1.0669x over previous
#include <cuda_runtime.h>
#include <math.h>

#define MAXB 8192
#define NS   16
#define SEG  8
#define D128 128
#define MARGIN 0.8f
#define EPS 1e-6f

__device__ float g_sq[MAXB];
__device__ int   g_start[NS + 1];
__device__ int   g_order[MAXB];
__device__ float g_pV[SEG * MAXB];
__device__ int   g_pI[SEG * MAXB];
__device__ float g_nV[SEG * MAXB];
__device__ int   g_nI[SEG * MAXB];
__device__ float g_blkL[MAXB / 8];
__device__ float g_blkV[MAXB / 8];

// ---------------- K1: per-row squared norm (no atomics) ----------------
__global__ void k_prep(const float* __restrict__ emb, int B) {
    int row = blockIdx.x * (blockDim.x >> 5) + (threadIdx.x >> 5);
    if (row >= B) return;
    int lane = threadIdx.x & 31;
    const float4 v4 = reinterpret_cast<const float4*>(emb + (size_t)row * D128)[lane];
    float s = v4.x * v4.x + v4.y * v4.y + v4.z * v4.z + v4.w * v4.w;
    #pragma unroll
    for (int off = 16; off > 0; off >>= 1) s += __shfl_xor_sync(0xffffffff, s, off);
    if (lane == 0) g_sq[row] = s;
}

// ---------------- K2: deterministic counting sort by subject ----------------
// One block, 1024 threads = 32 warps. Warp w owns rows [w*R, (w+1)*R).
// Per-warp stable ranks via ballot; cross-warp exclusive scan; then scatter.
__global__ void __launch_bounds__(1024) k_setup(const int* __restrict__ sbj, int B) {
    __shared__ unsigned short lrank[MAXB];
    __shared__ int whist[32][NS];
    __shared__ int woff[32][NS];
    __shared__ int sbase[NS + 1];

    const int tid = threadIdx.x;
    const int w = tid >> 5, lane = tid & 31;
    const int R = (B + 31) / 32;           // rows per warp
    const int base = w * R;
    const unsigned full = 0xffffffffu;

    int wcnt = 0;                           // lane L (<NS) holds running count of subject L
    for (int chunk = 0; chunk < R; chunk += 32) {
        int i = base + chunk + lane;
        int s = NS;                         // sentinel: matches nothing
        if (i < B) { s = sbj[i]; s = min(max(s, 0), NS - 1); }
        unsigned myMask = 0u;
        int addBits = 0;
        #pragma unroll
        for (int t = 0; t < NS; t++) {
            unsigned m = __ballot_sync(full, s == t);
            if (s == t) myMask = m;
            if (lane == t) addBits = __popc(m);
        }
        if (i < B) {
            int before = __shfl_sync(full, wcnt, s) + __popc(myMask & ((1u << lane) - 1u));
            lrank[i] = (unsigned short)before;
        }
        wcnt += addBits;
    }
    if (lane < NS) whist[w][lane] = wcnt;
    __syncthreads();

    // Cross-warp exclusive scan per subject: warp s scans whist[0..31][s].
    if (w < NS) {
        int v = whist[lane][w];
        int inc = v;
        #pragma unroll
        for (int off = 1; off < 32; off <<= 1) {
            int n = __shfl_up_sync(full, inc, off);
            if (lane >= off) inc += n;
        }
        woff[lane][w] = inc - v;
        if (lane == 31) sbase[w + 1] = inc;  // subject total (temporarily)
    }
    __syncthreads();
    if (tid == 0) {
        int acc = 0;
        for (int s = 0; s < NS; s++) {
            int tot = sbase[s + 1];
            sbase[s] = acc;
            g_start[s] = acc;
            acc += tot;
        }
        sbase[NS] = acc;
        g_start[NS] = acc;
    }
    __syncthreads();

    for (int chunk = 0; chunk < R; chunk += 32) {
        int i = base + chunk + lane;
        if (i < B) {
            int s = sbj[i]; s = min(max(s, 0), NS - 1);
            int pos = sbase[s] + woff[w][s] + (int)lrank[i];
            g_order[pos] = i;
        }
    }
}

// ---------------- K3: segmented mining ----------------
// grid (B/32 row-tiles, SEG col-segments), 128 threads.
// Tile: 32 rows x 64 cols, thread grid 16(tx) x 8(ty), 4x4 per thread.
#define API 36
#define BPI 68

__global__ void __launch_bounds__(128) k_mine(const float* __restrict__ emb,
                                              const int* __restrict__ labels,
                                              const int* __restrict__ sbj, int B) {
    __shared__ float As[D128 * API];          // full-K A tile, transposed
    __shared__ float Bs[64 * BPI];            // half-K B tile, transposed
    __shared__ int   rId[32], rLab[32], rSbj[32];
    __shared__ float rSq[32];
    __shared__ int   cJ[64], cLab[64], cSbj[64];
    __shared__ float cSq[64];
    __shared__ float redV[32 * 16];
    __shared__ int   redI[32 * 16];
    __shared__ int   sJlo, sJhi;

    const int tid = threadIdx.x;
    const int tileBase = blockIdx.x * 32;
    const int seg = blockIdx.y;

    if (tid < 32) {
        int i = g_order[tileBase + tid];
        rId[tid] = i;
        rLab[tid] = labels[i];
        int s = sbj[i]; s = min(max(s, 0), NS - 1);
        rSbj[tid] = s;
        rSq[tid] = g_sq[i];
    }
    __syncthreads();
    if (tid == 0) {
        int lo = g_start[rSbj[0]], hi = g_start[rSbj[0] + 1];
        for (int r = 1; r < 32; r++) {
            lo = min(lo, g_start[rSbj[r]]);
            hi = max(hi, g_start[rSbj[r] + 1]);
        }
        sJlo = lo; sJhi = hi;
    }
    // Load full A tile transposed, float4 gmem reads (32 rows x 32 float4).
    for (int idx = tid; idx < 32 * 32; idx += 128) {
        int r = idx >> 5, kq = idx & 31;
        const float4 v = reinterpret_cast<const float4*>(emb + (size_t)rId[r] * D128)[kq];
        As[(kq * 4 + 0) * API + r] = v.x;
        As[(kq * 4 + 1) * API + r] = v.y;
        As[(kq * 4 + 2) * API + r] = v.z;
        As[(kq * 4 + 3) * API + r] = v.w;
    }
    __syncthreads();

    const int tx = tid & 15, ty = tid >> 4;
    float bpV[4], bnV[4];
    int   bpI[4], bnI[4];
    #pragma unroll
    for (int r = 0; r < 4; r++) { bpV[r] = -3.0e38f; bnV[r] = 3.0e38f; bpI[r] = -1; bnI[r] = -1; }

    const int len = sJhi - sJlo;
    const int per = (len + SEG - 1) / SEG;
    const int lo  = sJlo + seg * per;
    const int hi  = min(lo + per, sJhi);

    for (int jc = lo; jc < hi; jc += 64) {
        const int nj = min(64, hi - jc);
        __syncthreads();     // previous selection done reading col meta
        if (tid < 64) {
            if (tid < nj) {
                int j = g_order[jc + tid];
                cJ[tid] = j; cLab[tid] = labels[j];
                int s = sbj[j]; cSbj[tid] = min(max(s, 0), NS - 1);
                cSq[tid] = g_sq[j];
            } else { cJ[tid] = -1; cSbj[tid] = -9; }
        }

        float acc[4][4];
        #pragma unroll
        for (int r = 0; r < 4; r++)
            #pragma unroll
            for (int c = 0; c < 4; c++) acc[r][c] = 0.f;

        #pragma unroll
        for (int kh = 0; kh < D128; kh += 64) {
            __syncthreads();   // prior compute done reading Bs
            // Load 64 cols x 64 k as float4 (64 x 16 float4), transpose into Bs.
            for (int idx = tid; idx < 64 * 16; idx += 128) {
                int c = idx >> 4, kq = idx & 15;
                float4 v = make_float4(0.f, 0.f, 0.f, 0.f);
                if (c < nj)
                    v = reinterpret_cast<const float4*>(emb + (size_t)g_order[jc + c] * D128 + kh)[kq];
                Bs[(kq * 4 + 0) * BPI + c] = v.x;
                Bs[(kq * 4 + 1) * BPI + c] = v.y;
                Bs[(kq * 4 + 2) * BPI + c] = v.z;
                Bs[(kq * 4 + 3) * BPI + c] = v.w;
            }
            __syncthreads();

            #pragma unroll 4
            for (int k = 0; k < 64; k++) {
                const float4 a = *reinterpret_cast<const float4*>(&As[(kh + k) * API + 4 * ty]);
                const float4 b = *reinterpret_cast<const float4*>(&Bs[k * BPI + 4 * tx]);
                float av[4] = {a.x, a.y, a.z, a.w};
                float bv[4] = {b.x, b.y, b.z, b.w};
                #pragma unroll
                for (int r = 0; r < 4; r++)
                    #pragma unroll
                    for (int c = 0; c < 4; c++)
                        acc[r][c] = fmaf(av[r], bv[c], acc[r][c]);
            }
        }

        #pragma unroll
        for (int r = 0; r < 4; r++) {
            int rr = 4 * ty + r;
            #pragma unroll
            for (int c = 0; c < 4; c++) {
                int cc = 4 * tx + c;
                if (cc >= nj) continue;
                if (cSbj[cc] != rSbj[rr]) continue;
                int j = cJ[cc];
                float d2 = rSq[rr] + cSq[cc] - 2.f * acc[r][c];
                if (cLab[cc] == rLab[rr]) {
                    if (j != rId[rr] && d2 > bpV[r]) { bpV[r] = d2; bpI[r] = j; }
                } else {
                    if (d2 < bnV[r]) { bnV[r] = d2; bnI[r] = j; }
                }
            }
        }
    }

    // Reduce across 16 tx threads per row: positives
    __syncthreads();
    #pragma unroll
    for (int r = 0; r < 4; r++) { redV[(4 * ty + r) * 16 + tx] = bpV[r]; redI[(4 * ty + r) * 16 + tx] = bpI[r]; }
    __syncthreads();
    if (tid < 32) {
        float bv = -3.0e38f; int bi = -1;
        #pragma unroll
        for (int t = 0; t < 16; t++) {
            float v = redV[tid * 16 + t];
            if (v > bv) { bv = v; bi = redI[tid * 16 + t]; }
        }
        g_pV[seg * MAXB + rId[tid]] = bv;
        g_pI[seg * MAXB + rId[tid]] = bi;
    }
    __syncthreads();
    // negatives
    #pragma unroll
    for (int r = 0; r < 4; r++) { redV[(4 * ty + r) * 16 + tx] = bnV[r]; redI[(4 * ty + r) * 16 + tx] = bnI[r]; }
    __syncthreads();
    if (tid < 32) {
        float bv = 3.0e38f; int bi = -1;
        #pragma unroll
        for (int t = 0; t < 16; t++) {
            float v = redV[tid * 16 + t];
            if (v < bv) { bv = v; bi = redI[tid * 16 + t]; }
        }
        g_nV[seg * MAXB + rId[tid]] = bv;
        g_nI[seg * MAXB + rId[tid]] = bi;
    }
}

// ---------------- K4: merge segments + triplet epilogue ----------------
__global__ void __launch_bounds__(256) k_merge(const float* __restrict__ emb, int B) {
    __shared__ float sL[8], sV[8];
    int w = threadIdx.x >> 5, lane = threadIdx.x & 31;
    int i = blockIdx.x * 8 + w;
    float per = 0.f, val = 0.f;
    if (i < B) {
        int bpI = -1, bnI = -1;
        if (lane == 0) {
            float bpV = -3.0e38f, bnV = 3.0e38f;
            #pragma unroll
            for (int s = 0; s < SEG; s++) {
                float pv = g_pV[s * MAXB + i]; int pi = g_pI[s * MAXB + i];
                if (pi >= 0 && pv > bpV) { bpV = pv; bpI = pi; }
                float nv = g_nV[s * MAXB + i]; int ni = g_nI[s * MAXB + i];
                if (ni >= 0 && nv < bnV) { bnV = nv; bnI = ni; }
            }
        }
        bpI = __shfl_sync(0xffffffff, bpI, 0);
        bnI = __shfl_sync(0xffffffff, bnI, 0);
        if (bpI >= 0 && bnI >= 0) {
            const float4 a = reinterpret_cast<const float4*>(emb + (size_t)i   * D128)[lane];
            const float4 p = reinterpret_cast<const float4*>(emb + (size_t)bpI * D128)[lane];
            const float4 n = reinterpret_cast<const float4*>(emb + (size_t)bnI * D128)[lane];
            float dx, sp, sn;
            dx = a.x - p.x + EPS; sp = dx * dx;
            dx = a.y - p.y + EPS; sp = fmaf(dx, dx, sp);
            dx = a.z - p.z + EPS; sp = fmaf(dx, dx, sp);
            dx = a.w - p.w + EPS; sp = fmaf(dx, dx, sp);
            dx = a.x - n.x + EPS; sn = dx * dx;
            dx = a.y - n.y + EPS; sn = fmaf(dx, dx, sn);
            dx = a.z - n.z + EPS; sn = fmaf(dx, dx, sn);
            dx = a.w - n.w + EPS; sn = fmaf(dx, dx, sn);
            #pragma unroll
            for (int off = 16; off > 0; off >>= 1) {
                sp += __shfl_xor_sync(0xffffffff, sp, off);
                sn += __shfl_xor_sync(0xffffffff, sn, off);
            }
            per = fmaxf(sqrtf(sp) - sqrtf(sn) + MARGIN, 0.f);
            val = 1.f;
        }
    }
    if (lane == 0) { sL[w] = per; sV[w] = val; }
    __syncthreads();
    if (threadIdx.x == 0) {
        float l = 0.f, v = 0.f;
        #pragma unroll
        for (int t = 0; t < 8; t++) { l += sL[t]; v += sV[t]; }
        g_blkL[blockIdx.x] = l;
        g_blkV[blockIdx.x] = v;
    }
}

// ---------------- K5: deterministic final reduction ----------------
__global__ void k_final(float* __restrict__ out, int nblk) {
    __shared__ float sl[1024], sv[1024];
    int tid = threadIdx.x;
    float l = 0.f, v = 0.f;
    for (int i = tid; i < nblk; i += 1024) { l += g_blkL[i]; v += g_blkV[i]; }
    sl[tid] = l; sv[tid] = v;
    __syncthreads();
    for (int off = 512; off > 0; off >>= 1) {
        if (tid < off) { sl[tid] += sl[tid + off]; sv[tid] += sv[tid + off]; }
        __syncthreads();
    }
    if (tid == 0) {
        float cnt = sv[0];
        out[0] = (cnt > 0.f) ? (sl[0] / fmaxf(cnt, 1.f)) : 0.f;
    }
}

extern "C" void kernel_launch(void* const* d_in, const int* in_sizes, int n_in,
                              void* d_out, int out_size) {
    const float* emb   = (const float*)d_in[0];
    const int* labels  = (const int*)d_in[1];
    const int* sbj     = (const int*)d_in[2];
    float* out = (float*)d_out;
    int B = in_sizes[1];

    k_prep<<<(B + 7) / 8, 256>>>(emb, B);
    k_setup<<<1, 1024>>>(sbj, B);
    dim3 mgrid(B / 32, SEG);
    k_mine<<<mgrid, 128>>>(emb, labels, sbj, B);
    int nblk = (B + 7) / 8;
    k_merge<<<nblk, 256>>>(emb, B);
    k_final<<<1, 1024>>>(out, nblk);
}

// round 4
// speedup vs baseline: 2.8714x; 1.0906x over previous
#include <cuda_runtime.h>
#include <math.h>

#define MAXB 8192
#define NS   16
#define D128 128
#define MARGIN 0.8f
#define EPS 1e-6f
#define MAXT 8512
#define TP 68          // smem k-pitch (floats)

__device__ float g_sq[MAXB];
__device__ int   g_start[NS + 1];
__device__ int   g_order[MAXB];
__device__ int4  g_tiles[MAXT];
__device__ int   g_T;
__device__ unsigned long long g_bestP[MAXB];
__device__ unsigned long long g_bestN[MAXB];
__device__ float g_blkL[MAXB / 8];
__device__ float g_blkV[MAXB / 8];

__device__ __forceinline__ unsigned mono(float f) {
    unsigned u = __float_as_uint(f);
    return (u & 0x80000000u) ? ~u : (u | 0x80000000u);
}

// ---------------- K1: row norms + init best keys ----------------
__global__ void k_prep(const float* __restrict__ emb, int B) {
    int row = blockIdx.x * (blockDim.x >> 5) + (threadIdx.x >> 5);
    if (row >= B) return;
    int lane = threadIdx.x & 31;
    const float4 v4 = reinterpret_cast<const float4*>(emb + (size_t)row * D128)[lane];
    float s = v4.x * v4.x + v4.y * v4.y + v4.z * v4.z + v4.w * v4.w;
    #pragma unroll
    for (int off = 16; off > 0; off >>= 1) s += __shfl_xor_sync(0xffffffff, s, off);
    if (lane == 0) {
        g_sq[row] = s;
        g_bestP[row] = 0ULL;
        g_bestN[row] = 0xFFFFFFFFFFFFFFFFULL;
    }
}

// ---------------- K2: deterministic counting sort + tile list ----------------
__global__ void __launch_bounds__(1024) k_setup(const int* __restrict__ sbj, int B) {
    __shared__ unsigned short lrank[MAXB];
    __shared__ int whist[32][NS];
    __shared__ int woff[32][NS];
    __shared__ int sbase[NS + 1];
    __shared__ int tbase[NS], tnt[NS];

    const int tid = threadIdx.x;
    const int w = tid >> 5, lane = tid & 31;
    const int R = (B + 31) / 32;
    const int base = w * R;
    const unsigned full = 0xffffffffu;

    int wcnt = 0;
    for (int chunk = 0; chunk < R; chunk += 32) {
        int i = base + chunk + lane;
        int s = NS;
        if (i < B) { s = sbj[i]; s = min(max(s, 0), NS - 1); }
        unsigned myMask = 0u;
        int addBits = 0;
        #pragma unroll
        for (int t = 0; t < NS; t++) {
            unsigned m = __ballot_sync(full, s == t);
            if (s == t) myMask = m;
            if (lane == t) addBits = __popc(m);
        }
        if (i < B) {
            int before = __shfl_sync(full, wcnt, s) + __popc(myMask & ((1u << lane) - 1u));
            lrank[i] = (unsigned short)before;
        }
        wcnt += addBits;
    }
    if (lane < NS) whist[w][lane] = wcnt;
    __syncthreads();

    if (w < NS) {
        int v = whist[lane][w];
        int inc = v;
        #pragma unroll
        for (int off = 1; off < 32; off <<= 1) {
            int n = __shfl_up_sync(full, inc, off);
            if (lane >= off) inc += n;
        }
        woff[lane][w] = inc - v;
        if (lane == 31) sbase[w + 1] = inc;
    }
    __syncthreads();
    if (tid == 0) {
        int acc = 0;
        for (int s = 0; s < NS; s++) {
            int tot = sbase[s + 1];
            sbase[s] = acc; g_start[s] = acc; acc += tot;
        }
        sbase[NS] = acc; g_start[NS] = acc;
    }
    __syncthreads();

    for (int chunk = 0; chunk < R; chunk += 32) {
        int i = base + chunk + lane;
        if (i < B) {
            int s = sbj[i]; s = min(max(s, 0), NS - 1);
            g_order[sbase[s] + woff[w][s] + (int)lrank[i]] = i;
        }
    }

    // ---- tile list: triangle of 64-row blocks per subject ----
    if (w == 0) {
        int ntri = 0, nt = 0;
        if (lane < NS) {
            int len = sbase[lane + 1] - sbase[lane];
            nt = (len + 63) >> 6;
            ntri = nt * (nt + 1) / 2;
        }
        int inc = ntri;
        #pragma unroll
        for (int off = 1; off < 32; off <<= 1) {
            int n = __shfl_up_sync(full, inc, off);
            if (lane >= off) inc += n;
        }
        if (lane < NS) { tbase[lane] = inc - ntri; tnt[lane] = nt; }
        if (lane == NS - 1) g_T = inc;
    }
    __syncthreads();

    if (w < NS) {
        int nt = tnt[w];
        int ntri = nt * (nt + 1) / 2;
        int lo = sbase[w], hi = sbase[w + 1];
        for (int i = lane; i < ntri; i += 32) {
            int a = 0, rem = i;
            while (rem >= nt - a) { rem -= nt - a; a++; }
            int b = a + rem;
            g_tiles[tbase[w] + i] = make_int4(lo + 64 * a, lo + 64 * b, hi, 0);
        }
    }
}

// ---------------- K3: triangle mining with packed atomics ----------------
// 256 threads, 64x64 tile, thread grid 16(tx) x 16(ty), 4x4 per thread.
__global__ void __launch_bounds__(256) k_mine(const float* __restrict__ emb,
                                              const int* __restrict__ labels) {
    __shared__ float As[64 * TP];   // [k][arow], half-K
    __shared__ float Bs[64 * TP];   // [k][brow], half-K
    __shared__ int   aId[64], aLab[64], bId[64], bLab[64];
    __shared__ float aSq[64], bSq[64];
    __shared__ float redV[64 * 16];
    __shared__ int   redI[64 * 16];

    const int tid = threadIdx.x;
    const int tx = tid & 15, ty = tid >> 4;
    const int T = g_T;

    for (int t = blockIdx.x; t < T; t += gridDim.x) {
        const int4 d = g_tiles[t];
        const int aBase = d.x, bBase = d.y, hi = d.z;
        const int na = min(64, hi - aBase);
        const int nb = min(64, hi - bBase);

        __syncthreads();   // previous tile fully done
        if (tid < 64) {
            if (tid < na) {
                int i = g_order[aBase + tid];
                aId[tid] = i; aLab[tid] = labels[i]; aSq[tid] = g_sq[i];
            } else { aId[tid] = -1; aLab[tid] = -2; aSq[tid] = 0.f; }
        } else if (tid < 128) {
            int c = tid - 64;
            if (c < nb) {
                int j = g_order[bBase + c];
                bId[c] = j; bLab[c] = labels[j]; bSq[c] = g_sq[j];
            } else { bId[c] = -1; bLab[c] = -3; bSq[c] = 0.f; }
        }
        __syncthreads();

        float acc[4][4];
        #pragma unroll
        for (int r = 0; r < 4; r++)
            #pragma unroll
            for (int c = 0; c < 4; c++) acc[r][c] = 0.f;

        #pragma unroll
        for (int kh = 0; kh < D128; kh += 64) {
            if (kh) __syncthreads();       // prior compute done reading tiles
            // fill As / Bs (transposed), float4 gmem reads
            for (int idx = tid; idx < 64 * 16; idx += 256) {
                int r = idx >> 4, kq = idx & 15;
                float4 v = make_float4(0.f, 0.f, 0.f, 0.f);
                if (r < na) v = reinterpret_cast<const float4*>(emb + (size_t)aId[r] * D128 + kh)[kq];
                As[(kq * 4 + 0) * TP + r] = v.x;
                As[(kq * 4 + 1) * TP + r] = v.y;
                As[(kq * 4 + 2) * TP + r] = v.z;
                As[(kq * 4 + 3) * TP + r] = v.w;
                float4 u = make_float4(0.f, 0.f, 0.f, 0.f);
                if (r < nb) u = reinterpret_cast<const float4*>(emb + (size_t)bId[r] * D128 + kh)[kq];
                Bs[(kq * 4 + 0) * TP + r] = u.x;
                Bs[(kq * 4 + 1) * TP + r] = u.y;
                Bs[(kq * 4 + 2) * TP + r] = u.z;
                Bs[(kq * 4 + 3) * TP + r] = u.w;
            }
            __syncthreads();

            #pragma unroll 4
            for (int k = 0; k < 64; k++) {
                const float4 a = *reinterpret_cast<const float4*>(&As[k * TP + 4 * ty]);
                const float4 b = *reinterpret_cast<const float4*>(&Bs[k * TP + 4 * tx]);
                float av[4] = {a.x, a.y, a.z, a.w};
                float bv[4] = {b.x, b.y, b.z, b.w};
                #pragma unroll
                for (int r = 0; r < 4; r++)
                    #pragma unroll
                    for (int c = 0; c < 4; c++)
                        acc[r][c] = fmaf(av[r], bv[c], acc[r][c]);
            }
        }

        // selection: row-side (rows of A) and col-side (rows of B)
        float rpV[4], rnV[4], cpV[4], cnV[4];
        int   rpI[4], rnI[4], cpI[4], cnI[4];
        #pragma unroll
        for (int q = 0; q < 4; q++) {
            rpV[q] = -3.0e38f; rnV[q] = 3.0e38f; rpI[q] = -1; rnI[q] = -1;
            cpV[q] = -3.0e38f; cnV[q] = 3.0e38f; cpI[q] = -1; cnI[q] = -1;
        }
        int   myALab[4], myBLab[4], myAId[4], myBId[4];
        float myASq[4], myBSq[4];
        #pragma unroll
        for (int q = 0; q < 4; q++) {
            myALab[q] = aLab[4 * ty + q]; myAId[q] = aId[4 * ty + q]; myASq[q] = aSq[4 * ty + q];
            myBLab[q] = bLab[4 * tx + q]; myBId[q] = bId[4 * tx + q]; myBSq[q] = bSq[4 * tx + q];
        }
        #pragma unroll
        for (int r = 0; r < 4; r++) {
            if (4 * ty + r >= na) continue;
            #pragma unroll
            for (int c = 0; c < 4; c++) {
                if (4 * tx + c >= nb) continue;
                float d2 = myASq[r] + myBSq[c] - 2.f * acc[r][c];
                bool sameL = (myALab[r] == myBLab[c]);
                bool self  = (myAId[r] == myBId[c]);
                if (sameL) {
                    if (!self) {
                        if (d2 > rpV[r]) { rpV[r] = d2; rpI[r] = myBId[c]; }
                        if (d2 > cpV[c]) { cpV[c] = d2; cpI[c] = myAId[r]; }
                    }
                } else {
                    if (d2 < rnV[r]) { rnV[r] = d2; rnI[r] = myBId[c]; }
                    if (d2 < cnV[c]) { cnV[c] = d2; cnI[c] = myAId[r]; }
                }
            }
        }

        // ---- pass 1: row-side positive (reduce over 16 tx) ----
        __syncthreads();
        #pragma unroll
        for (int r = 0; r < 4; r++) { redV[(4 * ty + r) * 16 + tx] = rpV[r]; redI[(4 * ty + r) * 16 + tx] = rpI[r]; }
        __syncthreads();
        if (tid < 64 && tid < na) {
            float bv = -3.0e38f; int bi = -1;
            #pragma unroll
            for (int q = 0; q < 16; q++) {
                float v = redV[tid * 16 + q];
                if (v > bv) { bv = v; bi = redI[tid * 16 + q]; }
            }
            if (bi >= 0) {
                unsigned long long key = ((unsigned long long)mono(bv) << 32) | (unsigned)(~bi);
                atomicMax(&g_bestP[aId[tid]], key);
            }
        }
        // ---- pass 2: row-side negative ----
        __syncthreads();
        #pragma unroll
        for (int r = 0; r < 4; r++) { redV[(4 * ty + r) * 16 + tx] = rnV[r]; redI[(4 * ty + r) * 16 + tx] = rnI[r]; }
        __syncthreads();
        if (tid < 64 && tid < na) {
            float bv = 3.0e38f; int bi = -1;
            #pragma unroll
            for (int q = 0; q < 16; q++) {
                float v = redV[tid * 16 + q];
                if (v < bv) { bv = v; bi = redI[tid * 16 + q]; }
            }
            if (bi >= 0) {
                unsigned long long key = ((unsigned long long)mono(bv) << 32) | (unsigned)bi;
                atomicMin(&g_bestN[aId[tid]], key);
            }
        }
        // ---- pass 3: col-side positive (reduce over 16 ty) ----
        __syncthreads();
        #pragma unroll
        for (int c = 0; c < 4; c++) { redV[(4 * tx + c) * 16 + ty] = cpV[c]; redI[(4 * tx + c) * 16 + ty] = cpI[c]; }
        __syncthreads();
        if (tid < 64 && tid < nb) {
            float bv = -3.0e38f; int bi = -1;
            #pragma unroll
            for (int q = 0; q < 16; q++) {
                float v = redV[tid * 16 + q];
                if (v > bv) { bv = v; bi = redI[tid * 16 + q]; }
            }
            if (bi >= 0) {
                unsigned long long key = ((unsigned long long)mono(bv) << 32) | (unsigned)(~bi);
                atomicMax(&g_bestP[bId[tid]], key);
            }
        }
        // ---- pass 4: col-side negative ----
        __syncthreads();
        #pragma unroll
        for (int c = 0; c < 4; c++) { redV[(4 * tx + c) * 16 + ty] = cnV[c]; redI[(4 * tx + c) * 16 + ty] = cnI[c]; }
        __syncthreads();
        if (tid < 64 && tid < nb) {
            float bv = 3.0e38f; int bi = -1;
            #pragma unroll
            for (int q = 0; q < 16; q++) {
                float v = redV[tid * 16 + q];
                if (v < bv) { bv = v; bi = redI[tid * 16 + q]; }
            }
            if (bi >= 0) {
                unsigned long long key = ((unsigned long long)mono(bv) << 32) | (unsigned)bi;
                atomicMin(&g_bestN[bId[tid]], key);
            }
        }
    }
}

// ---------------- K4: decode + triplet epilogue ----------------
__global__ void __launch_bounds__(256) k_merge(const float* __restrict__ emb, int B) {
    __shared__ float sL[8], sV[8];
    int w = threadIdx.x >> 5, lane = threadIdx.x & 31;
    int i = blockIdx.x * 8 + w;
    float per = 0.f, val = 0.f;
    if (i < B) {
        int bpI = -1, bnI = -1;
        if (lane == 0) {
            unsigned long long kp = g_bestP[i];
            unsigned long long kn = g_bestN[i];
            if (kp != 0ULL)                    bpI = (int)(~(unsigned)kp);
            if (kn != 0xFFFFFFFFFFFFFFFFULL)   bnI = (int)(unsigned)kn;
        }
        bpI = __shfl_sync(0xffffffff, bpI, 0);
        bnI = __shfl_sync(0xffffffff, bnI, 0);
        if (bpI >= 0 && bnI >= 0) {
            const float4 a = reinterpret_cast<const float4*>(emb + (size_t)i   * D128)[lane];
            const float4 p = reinterpret_cast<const float4*>(emb + (size_t)bpI * D128)[lane];
            const float4 n = reinterpret_cast<const float4*>(emb + (size_t)bnI * D128)[lane];
            float dx, sp, sn;
            dx = a.x - p.x + EPS; sp = dx * dx;
            dx = a.y - p.y + EPS; sp = fmaf(dx, dx, sp);
            dx = a.z - p.z + EPS; sp = fmaf(dx, dx, sp);
            dx = a.w - p.w + EPS; sp = fmaf(dx, dx, sp);
            dx = a.x - n.x + EPS; sn = dx * dx;
            dx = a.y - n.y + EPS; sn = fmaf(dx, dx, sn);
            dx = a.z - n.z + EPS; sn = fmaf(dx, dx, sn);
            dx = a.w - n.w + EPS; sn = fmaf(dx, dx, sn);
            #pragma unroll
            for (int off = 16; off > 0; off >>= 1) {
                sp += __shfl_xor_sync(0xffffffff, sp, off);
                sn += __shfl_xor_sync(0xffffffff, sn, off);
            }
            per = fmaxf(sqrtf(sp) - sqrtf(sn) + MARGIN, 0.f);
            val = 1.f;
        }
    }
    if (lane == 0) { sL[w] = per; sV[w] = val; }
    __syncthreads();
    if (threadIdx.x == 0) {
        float l = 0.f, v = 0.f;
        #pragma unroll
        for (int t = 0; t < 8; t++) { l += sL[t]; v += sV[t]; }
        g_blkL[blockIdx.x] = l;
        g_blkV[blockIdx.x] = v;
    }
}

// ---------------- K5: deterministic final reduction ----------------
__global__ void k_final(float* __restrict__ out, int nblk) {
    __shared__ float sl[1024], sv[1024];
    int tid = threadIdx.x;
    float l = 0.f, v = 0.f;
    for (int i = tid; i < nblk; i += 1024) { l += g_blkL[i]; v += g_blkV[i]; }
    sl[tid] = l; sv[tid] = v;
    __syncthreads();
    for (int off = 512; off > 0; off >>= 1) {
        if (tid < off) { sl[tid] += sl[tid + off]; sv[tid] += sv[tid + off]; }
        __syncthreads();
    }
    if (tid == 0) {
        float cnt = sv[0];
        out[0] = (cnt > 0.f) ? (sl[0] / fmaxf(cnt, 1.f)) : 0.f;
    }
}

extern "C" void kernel_launch(void* const* d_in, const int* in_sizes, int n_in,
                              void* d_out, int out_size) {
    const float* emb   = (const float*)d_in[0];
    const int* labels  = (const int*)d_in[1];
    const int* sbj     = (const int*)d_in[2];
    float* out = (float*)d_out;
    int B = in_sizes[1];

    k_prep<<<(B + 7) / 8, 256>>>(emb, B);
    k_setup<<<1, 1024>>>(sbj, B);
    k_mine<<<592, 256>>>(emb, labels);
    int nblk = (B + 7) / 8;
    k_merge<<<nblk, 256>>>(emb, B);
    k_final<<<1, 1024>>>(out, nblk);
}

// round 5
// speedup vs baseline: 4.2689x; 1.4867x over previous
#include <cuda_runtime.h>
#include <math.h>

#define MAXB 8192
#define NS   16
#define D128 128
#define MARGIN 0.8f
#define EPS 1e-6f
#define MAXT 8512
#define KH   32
#define AP2  132    // As2 pitch (floats): 128 dup-row floats + pad, 16B-aligned
#define BP   68     // Bs pitch (floats)

__device__ int   g_order[MAXB];
__device__ int4  g_tiles[MAXT];
__device__ int   g_T;
__device__ unsigned long long g_bestP[MAXB];
__device__ unsigned long long g_bestN[MAXB];
__device__ float g_blkL[1024];
__device__ float g_blkV[1024];
__device__ unsigned g_ticket;

__device__ __forceinline__ unsigned mono(float f) {
    unsigned u = __float_as_uint(f);
    return (u & 0x80000000u) ? ~u : (u | 0x80000000u);
}

#define FMA2(d, a, b) asm("fma.rn.f32x2 %0, %1, %2, %0;" : "+l"(d) : "l"(a), "l"(b))

// ---------------- K1: deterministic counting sort + tile list + init ----------------
__global__ void __launch_bounds__(1024) k_setup(const int* __restrict__ sbj, int B) {
    __shared__ unsigned short lrank[MAXB];
    __shared__ int whist[32][NS];
    __shared__ int woff[32][NS];
    __shared__ int sbase[NS + 1];
    __shared__ int tbase[NS], tnt[NS];

    const int tid = threadIdx.x;
    const int w = tid >> 5, lane = tid & 31;
    const int R = (B + 31) / 32;
    const int base = w * R;
    const unsigned full = 0xffffffffu;

    for (int i = tid; i < B; i += 1024) { g_bestP[i] = 0ULL; g_bestN[i] = 0ULL; }

    int wcnt = 0;
    for (int chunk = 0; chunk < R; chunk += 32) {
        int i = base + chunk + lane;
        int s = NS;
        if (i < B) { s = sbj[i]; s = min(max(s, 0), NS - 1); }
        unsigned myMask = 0u;
        int addBits = 0;
        #pragma unroll
        for (int t = 0; t < NS; t++) {
            unsigned m = __ballot_sync(full, s == t);
            if (s == t) myMask = m;
            if (lane == t) addBits = __popc(m);
        }
        if (i < B) {
            int before = __shfl_sync(full, wcnt, s) + __popc(myMask & ((1u << lane) - 1u));
            lrank[i] = (unsigned short)before;
        }
        wcnt += addBits;
    }
    if (lane < NS) whist[w][lane] = wcnt;
    __syncthreads();

    if (w < NS) {
        int v = whist[lane][w];
        int inc = v;
        #pragma unroll
        for (int off = 1; off < 32; off <<= 1) {
            int n = __shfl_up_sync(full, inc, off);
            if (lane >= off) inc += n;
        }
        woff[lane][w] = inc - v;
        if (lane == 31) sbase[w + 1] = inc;
    }
    __syncthreads();
    if (tid == 0) {
        int acc = 0;
        for (int s = 0; s < NS; s++) {
            int tot = sbase[s + 1];
            sbase[s] = acc; acc += tot;
        }
        sbase[NS] = acc;
    }
    __syncthreads();

    for (int chunk = 0; chunk < R; chunk += 32) {
        int i = base + chunk + lane;
        if (i < B) {
            int s = sbj[i]; s = min(max(s, 0), NS - 1);
            g_order[sbase[s] + woff[w][s] + (int)lrank[i]] = i;
        }
    }

    // ---- tile list: triangle of 64-row blocks per subject ----
    if (w == 0) {
        int ntri = 0, nt = 0;
        if (lane < NS) {
            int len = sbase[lane + 1] - sbase[lane];
            nt = (len + 63) >> 6;
            ntri = nt * (nt + 1) / 2;
        }
        int inc = ntri;
        #pragma unroll
        for (int off = 1; off < 32; off <<= 1) {
            int n = __shfl_up_sync(full, inc, off);
            if (lane >= off) inc += n;
        }
        if (lane < NS) { tbase[lane] = inc - ntri; tnt[lane] = nt; }
        if (lane == NS - 1) g_T = inc;
    }
    __syncthreads();

    if (w < NS) {
        int nt = tnt[w];
        int ntri = nt * (nt + 1) / 2;
        int lo = sbase[w], hi = sbase[w + 1];
        for (int i = lane; i < ntri; i += 32) {
            int a = 0, rem = i;
            while (rem >= nt - a) { rem -= nt - a; a++; }
            int b = a + rem;
            g_tiles[tbase[w] + i] = make_int4(lo + 64 * a, lo + 64 * b, hi, 0);
        }
    }
}

// ---------------- K2: triangle mining, packed f32x2 FMA ----------------
// 256 threads, 64x64 tile, thread grid 16(tx) x 16(ty), 4x4 per thread.
__global__ void __launch_bounds__(256) k_mine(const float* __restrict__ emb,
                                              const int* __restrict__ labels) {
    __shared__ float As2[KH * AP2];          // [k][2*row] duplicated A rows
    __shared__ float Bs[KH * BP];            // [k][row]
    __shared__ int   aId[64], aLab[64], bId[64], bLab[64];
    __shared__ float aSq[64], bSq[64];
    __shared__ unsigned long long redK[64 * 16];

    const int tid = threadIdx.x;
    const int tx = tid & 15, ty = tid >> 4;
    const int T = g_T;

    for (int t = blockIdx.x; t < T; t += gridDim.x) {
        const int4 dsc = g_tiles[t];
        const int aBase = dsc.x, bBase = dsc.y, hi = dsc.z;
        const int na = min(64, hi - aBase);
        const int nb = min(64, hi - bBase);

        __syncthreads();   // previous tile fully done
        if (tid < 64) {
            aSq[tid] = 0.f;
            if (tid < na) { int i = g_order[aBase + tid]; aId[tid] = i; aLab[tid] = labels[i]; }
            else { aId[tid] = -1; aLab[tid] = -2; }
        } else if (tid < 128) {
            int c = tid - 64;
            bSq[c] = 0.f;
            if (c < nb) { int j = g_order[bBase + c]; bId[c] = j; bLab[c] = labels[j]; }
            else { bId[c] = -1; bLab[c] = -3; }
        }

        unsigned long long acc2[4][2];
        #pragma unroll
        for (int r = 0; r < 4; r++) { acc2[r][0] = 0ULL; acc2[r][1] = 0ULL; }

        for (int kh = 0; kh < D128; kh += KH) {
            __syncthreads();   // ids ready / prior compute done
            // fill: 64 rows x 8 float4 each for A and B; accumulate norms
            #pragma unroll
            for (int it = 0; it < 2; it++) {
                int idx = tid + it * 256;
                int r = idx >> 3, kq = idx & 7;
                float4 v = make_float4(0.f, 0.f, 0.f, 0.f);
                float4 u = make_float4(0.f, 0.f, 0.f, 0.f);
                int ia = aId[r], ib = bId[r];
                if (ia >= 0) v = reinterpret_cast<const float4*>(emb + (size_t)ia * D128 + kh)[kq];
                if (ib >= 0) u = reinterpret_cast<const float4*>(emb + (size_t)ib * D128 + kh)[kq];
                int kb = kq * 4;
                *reinterpret_cast<float2*>(&As2[(kb + 0) * AP2 + 2 * r]) = make_float2(v.x, v.x);
                *reinterpret_cast<float2*>(&As2[(kb + 1) * AP2 + 2 * r]) = make_float2(v.y, v.y);
                *reinterpret_cast<float2*>(&As2[(kb + 2) * AP2 + 2 * r]) = make_float2(v.z, v.z);
                *reinterpret_cast<float2*>(&As2[(kb + 3) * AP2 + 2 * r]) = make_float2(v.w, v.w);
                Bs[(kb + 0) * BP + r] = u.x;
                Bs[(kb + 1) * BP + r] = u.y;
                Bs[(kb + 2) * BP + r] = u.z;
                Bs[(kb + 3) * BP + r] = u.w;
                float sa = v.x * v.x + v.y * v.y + v.z * v.z + v.w * v.w;
                float sb = u.x * u.x + u.y * u.y + u.z * u.z + u.w * u.w;
                #pragma unroll
                for (int off = 1; off < 8; off <<= 1) {
                    sa += __shfl_xor_sync(0xffffffffu, sa, off);
                    sb += __shfl_xor_sync(0xffffffffu, sb, off);
                }
                if (kq == 0) { aSq[r] += sa; bSq[r] += sb; }
            }
            __syncthreads();

            #pragma unroll 8
            for (int k = 0; k < KH; k++) {
                const ulonglong2 A0 = *reinterpret_cast<const ulonglong2*>(&As2[k * AP2 + 8 * ty]);
                const ulonglong2 A1 = *reinterpret_cast<const ulonglong2*>(&As2[k * AP2 + 8 * ty + 4]);
                const ulonglong2 Bq = *reinterpret_cast<const ulonglong2*>(&Bs[k * BP + 4 * tx]);
                FMA2(acc2[0][0], A0.x, Bq.x); FMA2(acc2[0][1], A0.x, Bq.y);
                FMA2(acc2[1][0], A0.y, Bq.x); FMA2(acc2[1][1], A0.y, Bq.y);
                FMA2(acc2[2][0], A1.x, Bq.x); FMA2(acc2[2][1], A1.x, Bq.y);
                FMA2(acc2[3][0], A1.y, Bq.x); FMA2(acc2[3][1], A1.y, Bq.y);
            }
        }

        // unpack accumulators
        float acc[4][4];
        #pragma unroll
        for (int r = 0; r < 4; r++) {
            asm("mov.b64 {%0,%1}, %2;" : "=f"(acc[r][0]), "=f"(acc[r][1]) : "l"(acc2[r][0]));
            asm("mov.b64 {%0,%1}, %2;" : "=f"(acc[r][2]), "=f"(acc[r][3]) : "l"(acc2[r][1]));
        }

        // selection: row-side (rows of A) and col-side (rows of B)
        float rpV[4], rnV[4], cpV[4], cnV[4];
        int   rpI[4], rnI[4], cpI[4], cnI[4];
        #pragma unroll
        for (int q = 0; q < 4; q++) {
            rpV[q] = -3.0e38f; rnV[q] = 3.0e38f; rpI[q] = -1; rnI[q] = -1;
            cpV[q] = -3.0e38f; cnV[q] = 3.0e38f; cpI[q] = -1; cnI[q] = -1;
        }
        #pragma unroll
        for (int r = 0; r < 4; r++) {
            int rr = 4 * ty + r;
            if (rr >= na) continue;
            int   aL = aLab[rr], aI = aId[rr];
            float aS = aSq[rr];
            #pragma unroll
            for (int c = 0; c < 4; c++) {
                int cc = 4 * tx + c;
                if (cc >= nb) continue;
                int bL = bLab[cc], bI = bId[cc];
                float d2 = aS + bSq[cc] - 2.f * acc[r][c];
                if (aL == bL) {
                    if (aI != bI) {
                        if (d2 > rpV[r]) { rpV[r] = d2; rpI[r] = bI; }
                        if (d2 > cpV[c]) { cpV[c] = d2; cpI[c] = aI; }
                    }
                } else {
                    if (d2 < rnV[r]) { rnV[r] = d2; rnI[r] = bI; }
                    if (d2 < cnV[c]) { cnV[c] = d2; cnI[c] = aI; }
                }
            }
        }

        // ---- 4 reduction passes with packed 64-bit keys (all max-scans) ----
        // pos key: mono(d2)<<32 | ~idx  (max => largest d2, then smallest idx)
        // neg key: ~mono(d2)<<32 | ~idx (max => smallest d2, then smallest idx)
        __syncthreads();
        #pragma unroll
        for (int r = 0; r < 4; r++)
            redK[(4 * ty + r) * 16 + tx] = (rpI[r] >= 0)
                ? (((unsigned long long)mono(rpV[r]) << 32) | (unsigned)(~rpI[r])) : 0ULL;
        __syncthreads();
        if (tid < 64 && tid < na) {
            unsigned long long bk = 0ULL;
            #pragma unroll
            for (int q = 0; q < 16; q++) { unsigned long long v = redK[tid * 16 + q]; if (v > bk) bk = v; }
            if (bk) atomicMax(&g_bestP[aId[tid]], bk);
        }
        __syncthreads();
        #pragma unroll
        for (int r = 0; r < 4; r++)
            redK[(4 * ty + r) * 16 + tx] = (rnI[r] >= 0)
                ? (((unsigned long long)(~mono(rnV[r])) << 32) | (unsigned)(~rnI[r])) : 0ULL;
        __syncthreads();
        if (tid < 64 && tid < na) {
            unsigned long long bk = 0ULL;
            #pragma unroll
            for (int q = 0; q < 16; q++) { unsigned long long v = redK[tid * 16 + q]; if (v > bk) bk = v; }
            if (bk) atomicMax(&g_bestN[aId[tid]], bk);
        }
        __syncthreads();
        #pragma unroll
        for (int c = 0; c < 4; c++)
            redK[(4 * tx + c) * 16 + ty] = (cpI[c] >= 0)
                ? (((unsigned long long)mono(cpV[c]) << 32) | (unsigned)(~cpI[c])) : 0ULL;
        __syncthreads();
        if (tid < 64 && tid < nb) {
            unsigned long long bk = 0ULL;
            #pragma unroll
            for (int q = 0; q < 16; q++) { unsigned long long v = redK[tid * 16 + q]; if (v > bk) bk = v; }
            if (bk) atomicMax(&g_bestP[bId[tid]], bk);
        }
        __syncthreads();
        #pragma unroll
        for (int c = 0; c < 4; c++)
            redK[(4 * tx + c) * 16 + ty] = (cnI[c] >= 0)
                ? (((unsigned long long)(~mono(cnV[c])) << 32) | (unsigned)(~cnI[c])) : 0ULL;
        __syncthreads();
        if (tid < 64 && tid < nb) {
            unsigned long long bk = 0ULL;
            #pragma unroll
            for (int q = 0; q < 16; q++) { unsigned long long v = redK[tid * 16 + q]; if (v > bk) bk = v; }
            if (bk) atomicMax(&g_bestN[bId[tid]], bk);
        }
    }
}

// ---------------- K3: decode + triplet epilogue + fused final reduction ----------------
__global__ void __launch_bounds__(256) k_merge(const float* __restrict__ emb,
                                               float* __restrict__ out, int B, int nblk) {
    __shared__ float sL[8], sV[8];
    __shared__ bool  lastBlk;
    int w = threadIdx.x >> 5, lane = threadIdx.x & 31;
    int i = blockIdx.x * 8 + w;
    float per = 0.f, val = 0.f;
    if (i < B) {
        int bpI = -1, bnI = -1;
        if (lane == 0) {
            unsigned long long kp = g_bestP[i];
            unsigned long long kn = g_bestN[i];
            if (kp) bpI = (int)(~(unsigned)kp);
            if (kn) bnI = (int)(~(unsigned)kn);
        }
        bpI = __shfl_sync(0xffffffff, bpI, 0);
        bnI = __shfl_sync(0xffffffff, bnI, 0);
        if (bpI >= 0 && bnI >= 0) {
            const float4 a = reinterpret_cast<const float4*>(emb + (size_t)i   * D128)[lane];
            const float4 p = reinterpret_cast<const float4*>(emb + (size_t)bpI * D128)[lane];
            const float4 n = reinterpret_cast<const float4*>(emb + (size_t)bnI * D128)[lane];
            float dx, sp, sn;
            dx = a.x - p.x + EPS; sp = dx * dx;
            dx = a.y - p.y + EPS; sp = fmaf(dx, dx, sp);
            dx = a.z - p.z + EPS; sp = fmaf(dx, dx, sp);
            dx = a.w - p.w + EPS; sp = fmaf(dx, dx, sp);
            dx = a.x - n.x + EPS; sn = dx * dx;
            dx = a.y - n.y + EPS; sn = fmaf(dx, dx, sn);
            dx = a.z - n.z + EPS; sn = fmaf(dx, dx, sn);
            dx = a.w - n.w + EPS; sn = fmaf(dx, dx, sn);
            #pragma unroll
            for (int off = 16; off > 0; off >>= 1) {
                sp += __shfl_xor_sync(0xffffffff, sp, off);
                sn += __shfl_xor_sync(0xffffffff, sn, off);
            }
            per = fmaxf(sqrtf(sp) - sqrtf(sn) + MARGIN, 0.f);
            val = 1.f;
        }
    }
    if (lane == 0) { sL[w] = per; sV[w] = val; }
    __syncthreads();
    if (threadIdx.x == 0) {
        float l = 0.f, v = 0.f;
        #pragma unroll
        for (int t = 0; t < 8; t++) { l += sL[t]; v += sV[t]; }
        g_blkL[blockIdx.x] = l;
        g_blkV[blockIdx.x] = v;
        __threadfence();
        lastBlk = (atomicInc(&g_ticket, (unsigned)(nblk - 1)) == (unsigned)(nblk - 1));
    }
    __syncthreads();
    if (lastBlk) {
        __shared__ float rl[256], rv[256];
        int tid = threadIdx.x;
        float l = 0.f, v = 0.f;
        for (int b = tid; b < nblk; b += 256) { l += g_blkL[b]; v += g_blkV[b]; }
        rl[tid] = l; rv[tid] = v;
        __syncthreads();
        for (int off = 128; off > 0; off >>= 1) {
            if (tid < off) { rl[tid] += rl[tid + off]; rv[tid] += rv[tid + off]; }
            __syncthreads();
        }
        if (tid == 0) {
            float cnt = rv[0];
            out[0] = (cnt > 0.f) ? (rl[0] / fmaxf(cnt, 1.f)) : 0.f;
        }
    }
}

extern "C" void kernel_launch(void* const* d_in, const int* in_sizes, int n_in,
                              void* d_out, int out_size) {
    const float* emb   = (const float*)d_in[0];
    const int* labels  = (const int*)d_in[1];
    const int* sbj     = (const int*)d_in[2];
    float* out = (float*)d_out;
    int B = in_sizes[1];

    k_setup<<<1, 1024>>>(sbj, B);
    k_mine<<<592, 256>>>(emb, labels);
    int nblk = (B + 7) / 8;
    k_merge<<<nblk, 256>>>(emb, out, B, nblk);
}